// round 3
// baseline (speedup 1.0000x reference)
#include <cuda_runtime.h>
#include <cstdint>

typedef unsigned long long ull;
#define FULL 0xffffffffu

constexpr int B_  = 16;
constexpr int N_  = 4096;
constexpr int NP_ = 1024;
constexpr int K_  = 32;
constexpr int CIN = 128;
constexpr int CG  = 131;   // 3 + 128
constexpr int C_  = 256;
constexpr int H_  = 4;
constexpr int D_  = 64;
constexpr int TC  = 768;   // 3*C
constexpr int RPB = 16;    // rows per block in mlp kernel

// scratch (device globals: allocation-free rule)
__device__ int   g_idx_buf[B_ * NP_ * K_];
__device__ float g_feat_buf[B_ * NP_ * C_];

extern __shared__ unsigned char dynsm[];

// ---------------- packed f32x2 helpers
__device__ __forceinline__ ull pk2(float a, float b) {
    ull r;
    asm("mov.b64 %0, {%1,%2};" : "=l"(r) : "f"(a), "f"(b));
    return r;
}
__device__ __forceinline__ void upk2(ull v, float& a, float& b) {
    asm("mov.b64 {%0,%1}, %2;" : "=f"(a), "=f"(b) : "l"(v));
}
__device__ __forceinline__ void fma2(ull& d, ull a, ull b) {
    asm("fma.rn.f32x2 %0, %1, %2, %3;" : "=l"(d) : "l"(a), "l"(b), "l"(d));
}

// ============================================================================
// K1: KNN. One warp per query, max-replacement top-32 (set-only; downstream is
// permutation invariant in neighbors).
// ============================================================================
__global__ void __launch_bounds__(256) knn_kernel(const float* __restrict__ xyz,
                                                  const float* __restrict__ nxyz) {
    float4* pts = reinterpret_cast<float4*>(dynsm);  // 4096 x {x,y,z,|.|^2}
    const int b = blockIdx.y;
    const float* xb = xyz + (long)b * N_ * 3;
    for (int j = threadIdx.x; j < N_; j += 256) {
        float x = xb[j * 3 + 0], y = xb[j * 3 + 1], z = xb[j * 3 + 2];
        pts[j] = make_float4(x, y, z, x * x + y * y + z * z);
    }
    __syncthreads();

    const int warp = threadIdx.x >> 5, lane = threadIdx.x & 31;
    const int p = blockIdx.x * 8 + warp;
    const float* q = nxyz + ((long)b * NP_ + p) * 3;
    const float qx = q[0], qy = q[1], qz = q[2];

    float4 c0 = pts[lane];
    float bestd = c0.w - 2.f * (qx * c0.x + qy * c0.y + qz * c0.z);
    int besti = lane;

    float curmax;
    int maxlane;
    {
        float v = bestd; int l = lane;
#pragma unroll
        for (int o = 16; o; o >>= 1) {
            float v2 = __shfl_xor_sync(FULL, v, o);
            int l2 = __shfl_xor_sync(FULL, l, o);
            if (v2 > v || (v2 == v && l2 < l)) { v = v2; l = l2; }
        }
        curmax = v; maxlane = l;
    }

    for (int j0 = K_; j0 < N_; j0 += K_) {
        float4 c = pts[j0 + lane];
        float d = c.w - 2.f * (qx * c.x + qy * c.y + qz * c.z);
        unsigned mset = __ballot_sync(FULL, d < curmax);
        while (mset) {
            int src = __ffs(mset) - 1;
            mset &= mset - 1;
            float cd = __shfl_sync(FULL, d, src);
            if (cd < curmax) {
                if (lane == maxlane) { bestd = cd; besti = j0 + src; }
                float v = bestd; int l = lane;
#pragma unroll
                for (int o = 16; o; o >>= 1) {
                    float v2 = __shfl_xor_sync(FULL, v, o);
                    int l2 = __shfl_xor_sync(FULL, l, o);
                    if (v2 > v || (v2 == v && l2 < l)) { v = v2; l = l2; }
                }
                curmax = v; maxlane = l;
            }
        }
    }
    g_idx_buf[((long)b * NP_ + p) * K_ + lane] = besti;
}

// ============================================================================
// K2: fused group -> LN -> Q GEMM -> collapsed K/V attention -> proj+dense.
// K GEMM collapse:  logits[h,r] = sum_i x[i,r] * z[h,i],  z = qm . Wk
// V GEMM collapse:  sat[t] = sum_i y[h,i] * Wv[i,t],      y = attnw . x
// ============================================================================
struct SmemAttn {
    float xsT[CG][34];      // LN'd grouped features, transposed (8B-aligned rows)
    float qm[C_];           // column-max of q
    float gmax[CG + 1];     // max over K of raw gf
    float z[H_][132];       // qm . Wk   (per head, per input feature)
    float attnw[H_][K_];    // softmax weights
    float y[H_][132];       // attnw . x (per head, per input feature)
    float sat[C_];          // attention output (pre-proj)
    float tmp2[2 * C_];     // proj / dense partial results
    int   nidx[K_];
    float q3[3];
};

__global__ void __launch_bounds__(256, 3) attn_kernel(
    const float* __restrict__ xyz, const float* __restrict__ nxyz,
    const float* __restrict__ featin, const float* __restrict__ wqkv,
    const float* __restrict__ projw, const float* __restrict__ projb,
    const float* __restrict__ densew, const float* __restrict__ denseb,
    const float* __restrict__ n1g, const float* __restrict__ n1b) {
    SmemAttn& s = *reinterpret_cast<SmemAttn*>(dynsm);
    const int t = threadIdx.x;
    const int grp = blockIdx.x;
    const int b = grp >> 10, p = grp & 1023;

    if (t < K_) s.nidx[t] = g_idx_buf[grp * K_ + t];
    if (t < 3) s.q3[t] = nxyz[((long)b * NP_ + p) * 3 + t];
    __syncthreads();

    // gather: relative xyz (cols 0..2) + features (cols 3..130)
    if (t < K_) {
        int j = s.nidx[t];
        const float* xp = xyz + ((long)b * N_ + j) * 3;
        s.xsT[0][t] = xp[0] - s.q3[0];
        s.xsT[1][t] = xp[1] - s.q3[1];
        s.xsT[2][t] = xp[2] - s.q3[2];
    }
    for (int e = t; e < K_ * CIN; e += 256) {
        int r = e >> 7, i = e & 127;
        s.xsT[3 + i][r] = featin[((long)b * N_ + s.nidx[r]) * CIN + i];
    }
    __syncthreads();

    // max over K of raw gf (dense branch) before LN overwrites
    if (t < CG) {
        float m = s.xsT[t][0];
#pragma unroll
        for (int r = 1; r < K_; ++r) m = fmaxf(m, s.xsT[t][r]);
        s.gmax[t] = m;
    }
    __syncthreads();

    // LayerNorm over CG=131 per row; warp w handles rows w, w+8, w+16, w+24
    {
        const int w = t >> 5, l = t & 31;
        for (int rr = 0; rr < 4; ++rr) {
            const int r = w + 8 * rr;
            float v[5];
            int kn = 0;
            float sum = 0.f;
            for (int ii = l; ii < CG; ii += 32) { v[kn] = s.xsT[ii][r]; sum += v[kn]; ++kn; }
#pragma unroll
            for (int o = 16; o; o >>= 1) sum += __shfl_xor_sync(FULL, sum, o);
            const float m = sum * (1.f / CG);
            float qv = 0.f;
            for (int k = 0; k < kn; ++k) { float d = v[k] - m; qv += d * d; }
#pragma unroll
            for (int o = 16; o; o >>= 1) qv += __shfl_xor_sync(FULL, qv, o);
            const float rs = rsqrtf(qv * (1.f / CG) + 1e-3f);
            kn = 0;
            for (int ii = l; ii < CG; ii += 32) {
                s.xsT[ii][r] = (v[kn] - m) * rs * n1g[ii] + n1b[ii];
                ++kn;
            }
        }
    }
    __syncthreads();

    // ---- Q pass: thread t owns q column t; only the column-max survives
    {
        ull aq[16];
#pragma unroll
        for (int rp = 0; rp < 16; ++rp) aq[rp] = 0ull;
        const float* wq = wqkv + t;
        float cw = wq[0];
#pragma unroll 1
        for (int i = 0; i < CG; ++i) {
            const int inx = (i + 1 < CG) ? i + 1 : i;
            const float nw = wq[(long)inx * TC];
            const ull w2 = pk2(cw, cw);
            const ull* xr = reinterpret_cast<const ull*>(s.xsT[i]);
#pragma unroll
            for (int rp = 0; rp < 16; ++rp) fma2(aq[rp], xr[rp], w2);
            cw = nw;
        }
        float mx = -1e30f;
#pragma unroll
        for (int rp = 0; rp < 16; ++rp) {
            float a, b2; upk2(aq[rp], a, b2);
            mx = fmaxf(mx, fmaxf(a, b2));
        }
        s.qm[t] = mx;
    }
    __syncthreads();

    // ---- z[h][i] = sum_d qm[h*64+d] * Wk[i, h*64+d]
    {
        const int h = t >> 6, i0 = t & 63;
        for (int i = i0; i < CG; i += 64) {
            const float4* wp = reinterpret_cast<const float4*>(wqkv + (long)i * TC + C_ + h * D_);
            float acc = 0.f;
#pragma unroll
            for (int d4 = 0; d4 < 16; ++d4) {
                const float4 w4 = wp[d4];
                acc += s.qm[h * D_ + 4 * d4 + 0] * w4.x
                     + s.qm[h * D_ + 4 * d4 + 1] * w4.y
                     + s.qm[h * D_ + 4 * d4 + 2] * w4.z
                     + s.qm[h * D_ + 4 * d4 + 3] * w4.w;
            }
            s.z[h][i] = acc;
        }
    }
    __syncthreads();

    // ---- logits + softmax: warp h (t<128), lane = row r
    if (t < 128) {
        const int h = t >> 5, r = t & 31;
        float acc = 0.f;
#pragma unroll 4
        for (int i = 0; i < CG; ++i) acc += s.xsT[i][r] * s.z[h][i];
        acc *= 0.0625f;  // C^-0.5
        float mx = acc;
#pragma unroll
        for (int o = 16; o; o >>= 1) mx = fmaxf(mx, __shfl_xor_sync(FULL, mx, o));
        const float e = expf(acc - mx);
        float ss = e;
#pragma unroll
        for (int o = 16; o; o >>= 1) ss += __shfl_xor_sync(FULL, ss, o);
        s.attnw[h][r] = e / ss;
    }
    __syncthreads();

    // ---- y[h][i] = sum_r attnw[h,r] * x[i,r]
    {
        const int h = t >> 6, i0 = t & 63;
        const ull* aw = reinterpret_cast<const ull*>(s.attnw[h]);
        for (int i = i0; i < CG; i += 64) {
            const ull* xr = reinterpret_cast<const ull*>(s.xsT[i]);
            ull acc = 0ull;
#pragma unroll
            for (int rp = 0; rp < 16; ++rp) fma2(acc, xr[rp], aw[rp]);
            float a, b2; upk2(acc, a, b2);
            s.y[h][i] = a + b2;
        }
    }
    __syncthreads();

    // ---- sat[t] = sum_i y[h][i] * Wv[i,t]
    {
        const int h = t >> 6;
        const float* wv = wqkv + 2 * C_ + t;
        float acc = 0.f;
#pragma unroll 4
        for (int i = 0; i < CG; ++i) acc += s.y[h][i] * wv[(long)i * TC];
        s.sat[t] = acc;
    }
    __syncthreads();

    // ---- proj (warps 0..3, col pairs) and dense branch (warps 4..7, col pairs)
    if (t < 128) {
        const int c0 = 2 * t;
        ull acc = 0ull;
        const float* wp = projw + c0;
#pragma unroll 4
        for (int i = 0; i < C_; ++i) {
            const ull w2 = *reinterpret_cast<const ull*>(wp + (long)i * C_);
            const float sv = s.sat[i];
            fma2(acc, pk2(sv, sv), w2);
        }
        float a, b2; upk2(acc, a, b2);
        s.tmp2[c0]     = fmaxf(a + projb[c0], 0.f);
        s.tmp2[c0 + 1] = fmaxf(b2 + projb[c0 + 1], 0.f);
    } else {
        const int c0 = 2 * (t - 128);
        ull acc = 0ull;
        const float* wd = densew + c0;
#pragma unroll 4
        for (int i = 0; i < CG; ++i) {
            const ull w2 = *reinterpret_cast<const ull*>(wd + (long)i * C_);
            const float gv = s.gmax[i];
            fma2(acc, pk2(gv, gv), w2);
        }
        float a, b2; upk2(acc, a, b2);
        s.tmp2[C_ + c0]     = fmaxf(a + denseb[c0], 0.f);
        s.tmp2[C_ + c0 + 1] = fmaxf(b2 + denseb[c0 + 1], 0.f);
    }
    __syncthreads();
    g_feat_buf[(long)grp * C_ + t] = s.tmp2[t] + s.tmp2[C_ + t];
}

// ============================================================================
// K3: LN2 -> fc1(relu) -> fc2 -> +feat. RPB=16 rows/block, register-tiled.
// ============================================================================
__global__ void __launch_bounds__(256) mlp_kernel(
    const float* __restrict__ fc1w, const float* __restrict__ fc1b,
    const float* __restrict__ fc2w, const float* __restrict__ fc2b,
    const float* __restrict__ n2g, const float* __restrict__ n2b,
    float* __restrict__ out) {
    ull*   lnDup = reinterpret_cast<ull*>(dynsm);                  // [256][17]
    float* hS    = reinterpret_cast<float*>(dynsm + 256 * 17 * 8); // [16][520]
    const int t = threadIdx.x;
    const long row0 = (long)blockIdx.x * RPB;

    // LN per row: warp w handles rows w and w+8
    {
        const int w = t >> 5, l = t & 31;
        for (int rr = 0; rr < 2; ++rr) {
            const int r = w + 8 * rr;
            const float* frow = g_feat_buf + (row0 + r) * C_;
            float v[8], sum = 0.f;
#pragma unroll
            for (int k = 0; k < 8; ++k) { v[k] = frow[l + 32 * k]; sum += v[k]; }
#pragma unroll
            for (int o = 16; o; o >>= 1) sum += __shfl_xor_sync(FULL, sum, o);
            const float m = sum * (1.f / C_);
            float qv = 0.f;
#pragma unroll
            for (int k = 0; k < 8; ++k) { float d = v[k] - m; qv += d * d; }
#pragma unroll
            for (int o = 16; o; o >>= 1) qv += __shfl_xor_sync(FULL, qv, o);
            const float rs = rsqrtf(qv * (1.f / C_) + 1e-3f);
#pragma unroll
            for (int k = 0; k < 8; ++k) {
                const int i = l + 32 * k;
                const float x = (v[k] - m) * rs * n2g[i] + n2b[i];
                lnDup[i * 17 + r] = pk2(x, x);
            }
        }
    }
    __syncthreads();

    const int q  = t >> 6;   // row group: rows 4q..4q+3
    const int cc = t & 63;

    // fc1: cols cc*8 .. cc*8+7 (4 col-pairs) x 4 rows
    {
        ull acc[4][4];
#pragma unroll
        for (int cp = 0; cp < 4; ++cp)
#pragma unroll
            for (int r = 0; r < 4; ++r) acc[cp][r] = 0ull;
        const float* wbase = fc1w + cc * 8;
#pragma unroll 1
        for (int i = 0; i < C_; ++i) {
            const ulonglong4 wv = *reinterpret_cast<const ulonglong4*>(wbase + (long)i * (2 * C_));
            const ull x0 = lnDup[i * 17 + 4 * q + 0];
            const ull x1 = lnDup[i * 17 + 4 * q + 1];
            const ull x2 = lnDup[i * 17 + 4 * q + 2];
            const ull x3 = lnDup[i * 17 + 4 * q + 3];
            fma2(acc[0][0], wv.x, x0); fma2(acc[0][1], wv.x, x1);
            fma2(acc[0][2], wv.x, x2); fma2(acc[0][3], wv.x, x3);
            fma2(acc[1][0], wv.y, x0); fma2(acc[1][1], wv.y, x1);
            fma2(acc[1][2], wv.y, x2); fma2(acc[1][3], wv.y, x3);
            fma2(acc[2][0], wv.z, x0); fma2(acc[2][1], wv.z, x1);
            fma2(acc[2][2], wv.z, x2); fma2(acc[2][3], wv.z, x3);
            fma2(acc[3][0], wv.w, x0); fma2(acc[3][1], wv.w, x1);
            fma2(acc[3][2], wv.w, x2); fma2(acc[3][3], wv.w, x3);
        }
        const float4 bA = *reinterpret_cast<const float4*>(fc1b + cc * 8);
        const float4 bB = *reinterpret_cast<const float4*>(fc1b + cc * 8 + 4);
        const float bias[8] = {bA.x, bA.y, bA.z, bA.w, bB.x, bB.y, bB.z, bB.w};
#pragma unroll
        for (int cp = 0; cp < 4; ++cp) {
            const int c0 = cc * 8 + 2 * cp;
#pragma unroll
            for (int r = 0; r < 4; ++r) {
                float a, b2; upk2(acc[cp][r], a, b2);
                hS[(4 * q + r) * 520 + c0]     = fmaxf(a + bias[2 * cp], 0.f);
                hS[(4 * q + r) * 520 + c0 + 1] = fmaxf(b2 + bias[2 * cp + 1], 0.f);
            }
        }
    }
    __syncthreads();

    // fc2: cols cc*4 .. cc*4+3 (2 col-pairs) x 4 rows, K=512
    {
        ull acc[2][4];
#pragma unroll
        for (int cp = 0; cp < 2; ++cp)
#pragma unroll
            for (int r = 0; r < 4; ++r) acc[cp][r] = 0ull;
        const float* wbase = fc2w + cc * 4;
#pragma unroll 2
        for (int j = 0; j < 2 * C_; ++j) {
            const ulonglong2 wv = *reinterpret_cast<const ulonglong2*>(wbase + (long)j * C_);
            const float h0 = hS[(4 * q + 0) * 520 + j];
            const float h1 = hS[(4 * q + 1) * 520 + j];
            const float h2 = hS[(4 * q + 2) * 520 + j];
            const float h3 = hS[(4 * q + 3) * 520 + j];
            const ull x0 = pk2(h0, h0), x1 = pk2(h1, h1), x2 = pk2(h2, h2), x3 = pk2(h3, h3);
            fma2(acc[0][0], wv.x, x0); fma2(acc[0][1], wv.x, x1);
            fma2(acc[0][2], wv.x, x2); fma2(acc[0][3], wv.x, x3);
            fma2(acc[1][0], wv.y, x0); fma2(acc[1][1], wv.y, x1);
            fma2(acc[1][2], wv.y, x2); fma2(acc[1][3], wv.y, x3);
        }
        const float4 bias = *reinterpret_cast<const float4*>(fc2b + cc * 4);
#pragma unroll
        for (int r = 0; r < 4; ++r) {
            const long row = row0 + 4 * q + r;
            const float4 res = *reinterpret_cast<const float4*>(g_feat_buf + row * C_ + cc * 4);
            float a0, a1, a2, a3;
            upk2(acc[0][r], a0, a1);
            upk2(acc[1][r], a2, a3);
            float4 o;
            o.x = a0 + bias.x + res.x;
            o.y = a1 + bias.y + res.y;
            o.z = a2 + bias.z + res.z;
            o.w = a3 + bias.w + res.w;
            *reinterpret_cast<float4*>(out + row * C_ + cc * 4) = o;
        }
    }
}

// ============================================================================
extern "C" void kernel_launch(void* const* d_in, const int* in_sizes, int n_in,
                              void* d_out, int out_size) {
    const float* xyz    = (const float*)d_in[0];
    const float* nxyz   = (const float*)d_in[1];
    const float* featin = (const float*)d_in[2];
    const float* wqkv   = (const float*)d_in[3];
    const float* projw  = (const float*)d_in[4];
    const float* projb  = (const float*)d_in[5];
    const float* densew = (const float*)d_in[6];
    const float* denseb = (const float*)d_in[7];
    const float* fc1w   = (const float*)d_in[8];
    const float* fc1b   = (const float*)d_in[9];
    const float* fc2w   = (const float*)d_in[10];
    const float* fc2b   = (const float*)d_in[11];
    const float* n1g    = (const float*)d_in[12];
    const float* n1b    = (const float*)d_in[13];
    const float* n2g    = (const float*)d_in[14];
    const float* n2b    = (const float*)d_in[15];
    float* out = (float*)d_out;

    (void)in_sizes; (void)n_in; (void)out_size;

    const int knn_smem  = N_ * (int)sizeof(float4);            // 64 KB
    const int attn_smem = (int)sizeof(SmemAttn);               // ~27 KB
    const int mlp_smem  = 256 * 17 * 8 + 16 * 520 * 4;         // ~68 KB
    cudaFuncSetAttribute(knn_kernel, cudaFuncAttributeMaxDynamicSharedMemorySize, knn_smem);
    cudaFuncSetAttribute(attn_kernel, cudaFuncAttributeMaxDynamicSharedMemorySize, attn_smem);
    cudaFuncSetAttribute(mlp_kernel, cudaFuncAttributeMaxDynamicSharedMemorySize, mlp_smem);

    knn_kernel<<<dim3(NP_ / 8, B_), 256, knn_smem>>>(xyz, nxyz);
    attn_kernel<<<B_ * NP_, 256, attn_smem>>>(xyz, nxyz, featin, wqkv, projw, projb,
                                              densew, denseb, n1g, n1b);
    mlp_kernel<<<B_ * NP_ / RPB, 256, mlp_smem>>>(fc1w, fc1b, fc2w, fc2b, n2g, n2b, out);
}

// round 5
// speedup vs baseline: 1.0544x; 1.0544x over previous
#include <cuda_runtime.h>
#include <cstdint>

typedef unsigned long long ull;
#define FULL 0xffffffffu

constexpr int B_  = 16;
constexpr int N_  = 4096;
constexpr int NP_ = 1024;
constexpr int K_  = 32;
constexpr int CIN = 128;
constexpr int CG  = 131;   // 3 + 128
constexpr int C_  = 256;
constexpr int H_  = 4;
constexpr int D_  = 64;
constexpr int TC  = 768;   // 3*C
constexpr int G_  = 4;     // groups per attn block
constexpr int GP  = 34;    // per-group sub-pitch (floats) in xsT row
constexpr int XP  = 138;   // xsT row pitch (floats): even (LDS.64) & 2-way-conflict STS
constexpr int RPB = 16;    // rows per block in mlp kernel

// scratch (device globals: allocation-free rule)
__device__ int   g_idx_buf[B_ * NP_ * K_];
__device__ float g_feat_buf[B_ * NP_ * C_];

extern __shared__ unsigned char dynsm[];

// ---------------- packed f32x2 helpers
__device__ __forceinline__ ull pk2(float a, float b) {
    ull r;
    asm("mov.b64 %0, {%1,%2};" : "=l"(r) : "f"(a), "f"(b));
    return r;
}
__device__ __forceinline__ void upk2(ull v, float& a, float& b) {
    asm("mov.b64 {%0,%1}, %2;" : "=f"(a), "=f"(b) : "l"(v));
}
__device__ __forceinline__ void fma2(ull& d, ull a, ull b) {
    asm("fma.rn.f32x2 %0, %1, %2, %3;" : "=l"(d) : "l"(a), "l"(b), "l"(d));
}

// ============================================================================
// K1: KNN. One warp per query, max-replacement top-32 (set-only; downstream is
// permutation invariant in neighbors). Value-only running max + ballot victim.
// ============================================================================
__global__ void __launch_bounds__(256) knn_kernel(const float* __restrict__ xyz,
                                                  const float* __restrict__ nxyz) {
    float4* pts = reinterpret_cast<float4*>(dynsm);  // 4096 x {x,y,z,|.|^2}
    const int b = blockIdx.y;
    const float* xb = xyz + (long)b * N_ * 3;
    for (int j = threadIdx.x; j < N_; j += 256) {
        float x = xb[j * 3 + 0], y = xb[j * 3 + 1], z = xb[j * 3 + 2];
        pts[j] = make_float4(x, y, z, x * x + y * y + z * z);
    }
    __syncthreads();

    const int warp = threadIdx.x >> 5, lane = threadIdx.x & 31;
    const int p = blockIdx.x * 8 + warp;
    const float* q = nxyz + ((long)b * NP_ + p) * 3;
    const float qx = q[0], qy = q[1], qz = q[2];

    float4 c0 = pts[lane];
    float bestd = c0.w - 2.f * (qx * c0.x + qy * c0.y + qz * c0.z);
    int besti = lane;

    float curmax = bestd;
#pragma unroll
    for (int o = 16; o; o >>= 1) curmax = fmaxf(curmax, __shfl_xor_sync(FULL, curmax, o));

    for (int j0 = K_; j0 < N_; j0 += K_) {
        float4 c = pts[j0 + lane];
        float d = c.w - 2.f * (qx * c.x + qy * c.y + qz * c.z);
        unsigned mset = __ballot_sync(FULL, d < curmax);
        while (mset) {
            int src = __ffs(mset) - 1;
            mset &= mset - 1;
            float cd = __shfl_sync(FULL, d, src);
            if (cd < curmax) {
                unsigned vict = __ballot_sync(FULL, bestd == curmax);
                int vl = __ffs(vict) - 1;
                if (lane == vl) { bestd = cd; besti = j0 + src; }
                float v = bestd;
#pragma unroll
                for (int o = 16; o; o >>= 1) v = fmaxf(v, __shfl_xor_sync(FULL, v, o));
                curmax = v;
            }
        }
    }
    g_idx_buf[((long)b * NP_ + p) * K_ + lane] = besti;
}

// ============================================================================
// K2: fused group -> LN -> Q GEMM -> collapsed K/V attention -> proj+dense,
// processing G_=4 groups per block so weight streams are L1/L2-amortized 4x.
// All vector-accessed members are kept 16B-aligned (pad0 after xsT).
// ============================================================================
struct __align__(16) SmemAttn {
    float xsT[CG][XP];          // 4 groups x (32 rows + pad), transposed (72312 B)
    float pad0[2];              // -> qm at 72320 B (16B aligned)
    float qm[G_][C_];           // column-max of q, per group            (+4096)
    float gmax[G_][132];        // max over K of raw gf, per group       (+2112)
    float z[G_][H_][132];       // qm . Wk                               (+8448)
    float y[G_][H_][132];       // attnw . x                             (+8448)
    float attnw[G_][H_][K_];    // softmax weights                       (+2048)
    float sat[G_][C_];          // attention output (pre-proj)           (+4096)
    int   nidx[G_][K_];
    float q3[G_][4];
};

__global__ void __launch_bounds__(256, 2) attn_kernel(
    const float* __restrict__ xyz, const float* __restrict__ nxyz,
    const float* __restrict__ featin, const float* __restrict__ wqkv,
    const float* __restrict__ projw, const float* __restrict__ projb,
    const float* __restrict__ densew, const float* __restrict__ denseb,
    const float* __restrict__ n1g, const float* __restrict__ n1b) {
    SmemAttn& s = *reinterpret_cast<SmemAttn*>(dynsm);
    const int t = threadIdx.x;
    const int grp0 = blockIdx.x * G_;
    const int b = grp0 >> 10, p0 = grp0 & 1023;

    if (t < G_ * K_) {
        int g = t >> 5, r = t & 31;
        s.nidx[g][r] = g_idx_buf[(long)(grp0 + g) * K_ + r];
    }
    if (t < G_ * 3) {
        int g = t / 3, c = t % 3;
        s.q3[g][c] = nxyz[((long)b * NP_ + p0 + g) * 3 + c];
    }
    __syncthreads();

    // gather: relative xyz (rows 0..2) + features (rows 3..130)
    if (t < G_ * K_) {
        int g = t >> 5, r = t & 31;
        int j = s.nidx[g][r];
        const float* xp = xyz + ((long)b * N_ + j) * 3;
        s.xsT[0][g * GP + r] = xp[0] - s.q3[g][0];
        s.xsT[1][g * GP + r] = xp[1] - s.q3[g][1];
        s.xsT[2][g * GP + r] = xp[2] - s.q3[g][2];
    }
    for (int e = t; e < G_ * K_ * CIN; e += 256) {
        int g = e >> 12, r = (e >> 7) & 31, i = e & 127;
        s.xsT[3 + i][g * GP + r] = featin[((long)b * N_ + s.nidx[g][r]) * CIN + i];
    }
    __syncthreads();

    // max over K of raw gf (dense branch) before LN overwrites
    for (int e = t; e < G_ * CG; e += 256) {
        int g = e / CG, i = e - g * CG;
        float m = s.xsT[i][g * GP];
#pragma unroll
        for (int r = 1; r < K_; ++r) m = fmaxf(m, s.xsT[i][g * GP + r]);
        s.gmax[g][i] = m;
    }
    __syncthreads();

    // LayerNorm over CG=131 per row; warp w owns rows w+8k (128 rows total)
    {
        const int w = t >> 5, l = t & 31;
        for (int k = 0; k < 16; ++k) {
            const int row = w + 8 * k;
            const int g = row >> 5, r = row & 31;
            float v[5];
            int kn = 0;
            float sum = 0.f;
            for (int ii = l; ii < CG; ii += 32) { v[kn] = s.xsT[ii][g * GP + r]; sum += v[kn]; ++kn; }
#pragma unroll
            for (int o = 16; o; o >>= 1) sum += __shfl_xor_sync(FULL, sum, o);
            const float m = sum * (1.f / CG);
            float qv = 0.f;
            for (int kk = 0; kk < kn; ++kk) { float d = v[kk] - m; qv += d * d; }
#pragma unroll
            for (int o = 16; o; o >>= 1) qv += __shfl_xor_sync(FULL, qv, o);
            const float rs = rsqrtf(qv * (1.f / CG) + 1e-3f);
            kn = 0;
            for (int ii = l; ii < CG; ii += 32) {
                s.xsT[ii][g * GP + r] = (v[kn] - m) * rs * n1g[ii] + n1b[ii];
                ++kn;
            }
        }
    }
    __syncthreads();

    // ---- Q pass: 4 column chunks; thread = (group gq, col chunk-lane cLo).
    // Warps of different groups share the same weight lines via L1.
    {
        const int cLo = t & 63;
        const int gq = t >> 6;
        for (int ch = 0; ch < 4; ++ch) {
            const int col = ch * 64 + cLo;
            const float* wq = wqkv + col;
            ull aq[16];
#pragma unroll
            for (int rp = 0; rp < 16; ++rp) aq[rp] = 0ull;
            float cw = wq[0];
#pragma unroll 1
            for (int i = 0; i < CG; ++i) {
                const int inx = (i + 1 < CG) ? i + 1 : i;
                const float nw = wq[(long)inx * TC];
                const ull w2 = pk2(cw, cw);
                const ull* xr = reinterpret_cast<const ull*>(&s.xsT[i][gq * GP]);
#pragma unroll
                for (int rp = 0; rp < 16; ++rp) fma2(aq[rp], xr[rp], w2);
                cw = nw;
            }
            float mx = -1e30f;
#pragma unroll
            for (int rp = 0; rp < 16; ++rp) {
                float a, b2; upk2(aq[rp], a, b2);
                mx = fmaxf(mx, fmaxf(a, b2));
            }
            s.qm[gq][col] = mx;
        }
    }
    __syncthreads();

    // ---- z[g][h][i] = sum_d qm[g][h*64+d] * Wk[i][h*64+d]; warp-per-i, coalesced rows
    {
        const int w = t >> 5, l = t & 31;
        float4 qa[G_], qb[G_];
#pragma unroll
        for (int g = 0; g < G_; ++g) {
            qa[g] = reinterpret_cast<const float4*>(s.qm[g])[l];
            qb[g] = reinterpret_cast<const float4*>(s.qm[g])[32 + l];
        }
        for (int i = w; i < CG; i += 8) {
            const float4* wr = reinterpret_cast<const float4*>(wqkv + (long)i * TC + C_);
            const float4 w0 = wr[l];
            const float4 w1 = wr[32 + l];
            float s0[G_], s1[G_];
#pragma unroll
            for (int g = 0; g < G_; ++g) {
                s0[g] = w0.x * qa[g].x + w0.y * qa[g].y + w0.z * qa[g].z + w0.w * qa[g].w;
                s1[g] = w1.x * qb[g].x + w1.y * qb[g].y + w1.z * qb[g].z + w1.w * qb[g].w;
            }
#pragma unroll
            for (int o = 8; o; o >>= 1) {
#pragma unroll
                for (int g = 0; g < G_; ++g) {
                    s0[g] += __shfl_xor_sync(FULL, s0[g], o);
                    s1[g] += __shfl_xor_sync(FULL, s1[g], o);
                }
            }
            if ((l & 15) == 0) {
                const int h0 = l >> 4;
#pragma unroll
                for (int g = 0; g < G_; ++g) {
                    s.z[g][h0][i]     = s0[g];
                    s.z[g][h0 + 2][i] = s1[g];
                }
            }
        }
    }
    __syncthreads();

    // ---- logits + softmax: 16 (g,h) warp-slots on 8 warps (2 each, interleaved)
    {
        const int r = t & 31;
        const int wh0 = t >> 5, wh1 = wh0 + 8;
        const int g0 = wh0 >> 2, h0 = wh0 & 3;
        const int g1 = wh1 >> 2, h1 = wh1 & 3;
        float a0 = 0.f, a1 = 0.f;
#pragma unroll 4
        for (int i = 0; i < CG; ++i) {
            a0 += s.xsT[i][g0 * GP + r] * s.z[g0][h0][i];
            a1 += s.xsT[i][g1 * GP + r] * s.z[g1][h1][i];
        }
        a0 *= 0.0625f; a1 *= 0.0625f;
        float m0 = a0, m1 = a1;
#pragma unroll
        for (int o = 16; o; o >>= 1) {
            m0 = fmaxf(m0, __shfl_xor_sync(FULL, m0, o));
            m1 = fmaxf(m1, __shfl_xor_sync(FULL, m1, o));
        }
        const float e0 = expf(a0 - m0), e1 = expf(a1 - m1);
        float ss0 = e0, ss1 = e1;
#pragma unroll
        for (int o = 16; o; o >>= 1) {
            ss0 += __shfl_xor_sync(FULL, ss0, o);
            ss1 += __shfl_xor_sync(FULL, ss1, o);
        }
        s.attnw[g0][h0][r] = e0 / ss0;
        s.attnw[g1][h1][r] = e1 / ss1;
    }
    __syncthreads();

    // ---- y[g][h][i] = sum_r attnw[g][h][r] * x[i][r]
    for (int e = t; e < G_ * H_ * CG; e += 256) {
        const int i = e % CG;
        const int gh = e / CG;
        const int g = gh >> 2, h = gh & 3;
        const ull* aw = reinterpret_cast<const ull*>(s.attnw[g][h]);
        const ull* xr = reinterpret_cast<const ull*>(&s.xsT[i][g * GP]);
        ull acc = 0ull;
#pragma unroll
        for (int rp = 0; rp < 16; ++rp) fma2(acc, xr[rp], aw[rp]);
        float a, b2; upk2(acc, a, b2);
        s.y[g][h][i] = a + b2;
    }
    __syncthreads();

    // ---- sat[g][t] = sum_i y[g][h][i] * Wv[i][t]   (h = t>>6)
    {
        const int h = t >> 6;
        const float* wv = wqkv + 2 * C_ + t;
        float acc[G_] = {0.f, 0.f, 0.f, 0.f};
        float cw = wv[0];
#pragma unroll 1
        for (int i = 0; i < CG; ++i) {
            const int inx = (i + 1 < CG) ? i + 1 : i;
            const float nw = wv[(long)inx * TC];
#pragma unroll
            for (int g = 0; g < G_; ++g) acc[g] += s.y[g][h][i] * cw;
            cw = nw;
        }
#pragma unroll
        for (int g = 0; g < G_; ++g) s.sat[g][t] = acc[g];
    }
    __syncthreads();

    // ---- proj (relu) + dense (relu): thread = (col pair c0, group pair gp)
    {
        const int c0 = 2 * (t & 127);
        const int gp = t >> 7;                    // groups 2gp, 2gp+1
        ull accP0 = 0ull, accP1 = 0ull;
        const float* wp = projw + c0;
#pragma unroll 4
        for (int i = 0; i < C_; ++i) {
            const ull w2 = *reinterpret_cast<const ull*>(wp + (long)i * C_);
            const float v0 = s.sat[2 * gp][i], v1 = s.sat[2 * gp + 1][i];
            fma2(accP0, pk2(v0, v0), w2);
            fma2(accP1, pk2(v1, v1), w2);
        }
        ull accD0 = 0ull, accD1 = 0ull;
        const float* wd = densew + c0;
#pragma unroll 4
        for (int i = 0; i < CG; ++i) {
            const ull w2 = *reinterpret_cast<const ull*>(wd + (long)i * C_);
            const float v0 = s.gmax[2 * gp][i], v1 = s.gmax[2 * gp + 1][i];
            fma2(accD0, pk2(v0, v0), w2);
            fma2(accD1, pk2(v1, v1), w2);
        }
        const float pb0 = projb[c0], pb1 = projb[c0 + 1];
        const float db0 = denseb[c0], db1 = denseb[c0 + 1];
        float pa, pb, da, db;
        upk2(accP0, pa, pb); upk2(accD0, da, db);
        g_feat_buf[(long)(grp0 + 2 * gp) * C_ + c0]     = fmaxf(pa + pb0, 0.f) + fmaxf(da + db0, 0.f);
        g_feat_buf[(long)(grp0 + 2 * gp) * C_ + c0 + 1] = fmaxf(pb + pb1, 0.f) + fmaxf(db + db1, 0.f);
        upk2(accP1, pa, pb); upk2(accD1, da, db);
        g_feat_buf[(long)(grp0 + 2 * gp + 1) * C_ + c0]     = fmaxf(pa + pb0, 0.f) + fmaxf(da + db0, 0.f);
        g_feat_buf[(long)(grp0 + 2 * gp + 1) * C_ + c0 + 1] = fmaxf(pb + pb1, 0.f) + fmaxf(db + db1, 0.f);
    }
}

// ============================================================================
// K3: LN2 -> fc1(relu) -> fc2 -> +feat. RPB=16 rows/block, register-tiled.
// ============================================================================
__global__ void __launch_bounds__(256) mlp_kernel(
    const float* __restrict__ fc1w, const float* __restrict__ fc1b,
    const float* __restrict__ fc2w, const float* __restrict__ fc2b,
    const float* __restrict__ n2g, const float* __restrict__ n2b,
    float* __restrict__ out) {
    ull*   lnDup = reinterpret_cast<ull*>(dynsm);                  // [256][17]
    float* hS    = reinterpret_cast<float*>(dynsm + 256 * 17 * 8); // [16][520]
    const int t = threadIdx.x;
    const long row0 = (long)blockIdx.x * RPB;

    // LN per row: warp w handles rows w and w+8
    {
        const int w = t >> 5, l = t & 31;
        for (int rr = 0; rr < 2; ++rr) {
            const int r = w + 8 * rr;
            const float* frow = g_feat_buf + (row0 + r) * C_;
            float v[8], sum = 0.f;
#pragma unroll
            for (int k = 0; k < 8; ++k) { v[k] = frow[l + 32 * k]; sum += v[k]; }
#pragma unroll
            for (int o = 16; o; o >>= 1) sum += __shfl_xor_sync(FULL, sum, o);
            const float m = sum * (1.f / C_);
            float qv = 0.f;
#pragma unroll
            for (int k = 0; k < 8; ++k) { float d = v[k] - m; qv += d * d; }
#pragma unroll
            for (int o = 16; o; o >>= 1) qv += __shfl_xor_sync(FULL, qv, o);
            const float rs = rsqrtf(qv * (1.f / C_) + 1e-3f);
#pragma unroll
            for (int k = 0; k < 8; ++k) {
                const int i = l + 32 * k;
                const float x = (v[k] - m) * rs * n2g[i] + n2b[i];
                lnDup[i * 17 + r] = pk2(x, x);
            }
        }
    }
    __syncthreads();

    const int q  = t >> 6;   // row group: rows 4q..4q+3
    const int cc = t & 63;

    // fc1: cols cc*8 .. cc*8+7 (4 col-pairs) x 4 rows
    {
        ull acc[4][4];
#pragma unroll
        for (int cp = 0; cp < 4; ++cp)
#pragma unroll
            for (int r = 0; r < 4; ++r) acc[cp][r] = 0ull;
        const float* wbase = fc1w + cc * 8;
#pragma unroll 1
        for (int i = 0; i < C_; ++i) {
            const ulonglong4 wv = *reinterpret_cast<const ulonglong4*>(wbase + (long)i * (2 * C_));
            const ull x0 = lnDup[i * 17 + 4 * q + 0];
            const ull x1 = lnDup[i * 17 + 4 * q + 1];
            const ull x2 = lnDup[i * 17 + 4 * q + 2];
            const ull x3 = lnDup[i * 17 + 4 * q + 3];
            fma2(acc[0][0], wv.x, x0); fma2(acc[0][1], wv.x, x1);
            fma2(acc[0][2], wv.x, x2); fma2(acc[0][3], wv.x, x3);
            fma2(acc[1][0], wv.y, x0); fma2(acc[1][1], wv.y, x1);
            fma2(acc[1][2], wv.y, x2); fma2(acc[1][3], wv.y, x3);
            fma2(acc[2][0], wv.z, x0); fma2(acc[2][1], wv.z, x1);
            fma2(acc[2][2], wv.z, x2); fma2(acc[2][3], wv.z, x3);
            fma2(acc[3][0], wv.w, x0); fma2(acc[3][1], wv.w, x1);
            fma2(acc[3][2], wv.w, x2); fma2(acc[3][3], wv.w, x3);
        }
        const float4 bA = *reinterpret_cast<const float4*>(fc1b + cc * 8);
        const float4 bB = *reinterpret_cast<const float4*>(fc1b + cc * 8 + 4);
        const float bias[8] = {bA.x, bA.y, bA.z, bA.w, bB.x, bB.y, bB.z, bB.w};
#pragma unroll
        for (int cp = 0; cp < 4; ++cp) {
            const int c0 = cc * 8 + 2 * cp;
#pragma unroll
            for (int r = 0; r < 4; ++r) {
                float a, b2; upk2(acc[cp][r], a, b2);
                hS[(4 * q + r) * 520 + c0]     = fmaxf(a + bias[2 * cp], 0.f);
                hS[(4 * q + r) * 520 + c0 + 1] = fmaxf(b2 + bias[2 * cp + 1], 0.f);
            }
        }
    }
    __syncthreads();

    // fc2: cols cc*4 .. cc*4+3 (2 col-pairs) x 4 rows, K=512
    {
        ull acc[2][4];
#pragma unroll
        for (int cp = 0; cp < 2; ++cp)
#pragma unroll
            for (int r = 0; r < 4; ++r) acc[cp][r] = 0ull;
        const float* wbase = fc2w + cc * 4;
#pragma unroll 2
        for (int j = 0; j < 2 * C_; ++j) {
            const ulonglong2 wv = *reinterpret_cast<const ulonglong2*>(wbase + (long)j * C_);
            const float h0 = hS[(4 * q + 0) * 520 + j];
            const float h1 = hS[(4 * q + 1) * 520 + j];
            const float h2 = hS[(4 * q + 2) * 520 + j];
            const float h3 = hS[(4 * q + 3) * 520 + j];
            const ull x0 = pk2(h0, h0), x1 = pk2(h1, h1), x2 = pk2(h2, h2), x3 = pk2(h3, h3);
            fma2(acc[0][0], wv.x, x0); fma2(acc[0][1], wv.x, x1);
            fma2(acc[0][2], wv.x, x2); fma2(acc[0][3], wv.x, x3);
            fma2(acc[1][0], wv.y, x0); fma2(acc[1][1], wv.y, x1);
            fma2(acc[1][2], wv.y, x2); fma2(acc[1][3], wv.y, x3);
        }
        const float4 bias = *reinterpret_cast<const float4*>(fc2b + cc * 4);
#pragma unroll
        for (int r = 0; r < 4; ++r) {
            const long row = row0 + 4 * q + r;
            const float4 res = *reinterpret_cast<const float4*>(g_feat_buf + row * C_ + cc * 4);
            float a0, a1, a2, a3;
            upk2(acc[0][r], a0, a1);
            upk2(acc[1][r], a2, a3);
            float4 o;
            o.x = a0 + bias.x + res.x;
            o.y = a1 + bias.y + res.y;
            o.z = a2 + bias.z + res.z;
            o.w = a3 + bias.w + res.w;
            *reinterpret_cast<float4*>(out + row * C_ + cc * 4) = o;
        }
    }
}

// ============================================================================
extern "C" void kernel_launch(void* const* d_in, const int* in_sizes, int n_in,
                              void* d_out, int out_size) {
    const float* xyz    = (const float*)d_in[0];
    const float* nxyz   = (const float*)d_in[1];
    const float* featin = (const float*)d_in[2];
    const float* wqkv   = (const float*)d_in[3];
    const float* projw  = (const float*)d_in[4];
    const float* projb  = (const float*)d_in[5];
    const float* densew = (const float*)d_in[6];
    const float* denseb = (const float*)d_in[7];
    const float* fc1w   = (const float*)d_in[8];
    const float* fc1b   = (const float*)d_in[9];
    const float* fc2w   = (const float*)d_in[10];
    const float* fc2b   = (const float*)d_in[11];
    const float* n1g    = (const float*)d_in[12];
    const float* n1b    = (const float*)d_in[13];
    const float* n2g    = (const float*)d_in[14];
    const float* n2b    = (const float*)d_in[15];
    float* out = (float*)d_out;

    (void)in_sizes; (void)n_in; (void)out_size;

    const int knn_smem  = N_ * (int)sizeof(float4);            // 64 KB
    const int attn_smem = (int)sizeof(SmemAttn);               // ~100 KB
    const int mlp_smem  = 256 * 17 * 8 + 16 * 520 * 4;         // ~68 KB
    cudaFuncSetAttribute(knn_kernel, cudaFuncAttributeMaxDynamicSharedMemorySize, knn_smem);
    cudaFuncSetAttribute(attn_kernel, cudaFuncAttributeMaxDynamicSharedMemorySize, attn_smem);
    cudaFuncSetAttribute(mlp_kernel, cudaFuncAttributeMaxDynamicSharedMemorySize, mlp_smem);

    knn_kernel<<<dim3(NP_ / 8, B_), 256, knn_smem>>>(xyz, nxyz);
    attn_kernel<<<B_ * NP_ / G_, 256, attn_smem>>>(xyz, nxyz, featin, wqkv, projw, projb,
                                                   densew, denseb, n1g, n1b);
    mlp_kernel<<<B_ * NP_ / RPB, 256, mlp_smem>>>(fc1w, fc1b, fc2w, fc2b, n2g, n2b, out);
}

// round 6
// speedup vs baseline: 1.4079x; 1.3353x over previous
#include <cuda_runtime.h>
#include <cstdint>

typedef unsigned long long ull;
#define FULL 0xffffffffu

constexpr int B_  = 16;
constexpr int N_  = 4096;
constexpr int NP_ = 1024;
constexpr int K_  = 32;
constexpr int CIN = 128;
constexpr int CG  = 131;   // 3 + 128
constexpr int C_  = 256;
constexpr int H_  = 4;
constexpr int D_  = 64;
constexpr int TC  = 768;   // 3*C
constexpr int G_  = 4;     // groups per attn block
constexpr int GP  = 34;    // per-group sub-pitch (floats) in xsT row
constexpr int XP  = 138;   // xsT row pitch (floats)
constexpr int T_  = 512;   // attn threads
constexpr int RPB = 16;    // rows per block in mlp kernel

// scratch (device globals: allocation-free rule)
__device__ int   g_idx_buf[B_ * NP_ * K_];
__device__ float g_feat_buf[B_ * NP_ * C_];

extern __shared__ unsigned char dynsm[];

// ---------------- packed f32x2 helpers
__device__ __forceinline__ ull pk2(float a, float b) {
    ull r;
    asm("mov.b64 %0, {%1,%2};" : "=l"(r) : "f"(a), "f"(b));
    return r;
}
__device__ __forceinline__ void upk2(ull v, float& a, float& b) {
    asm("mov.b64 {%0,%1}, %2;" : "=f"(a), "=f"(b) : "l"(v));
}
__device__ __forceinline__ void fma2(ull& d, ull a, ull b) {
    asm("fma.rn.f32x2 %0, %1, %2, %3;" : "=l"(d) : "l"(a), "l"(b), "l"(d));
}

// ============================================================================
// K1: KNN. One warp per query, max-replacement top-32 (set-only).
// ============================================================================
__global__ void __launch_bounds__(256) knn_kernel(const float* __restrict__ xyz,
                                                  const float* __restrict__ nxyz) {
    float4* pts = reinterpret_cast<float4*>(dynsm);  // 4096 x {x,y,z,|.|^2}
    const int b = blockIdx.y;
    const float* xb = xyz + (long)b * N_ * 3;
    for (int j = threadIdx.x; j < N_; j += 256) {
        float x = xb[j * 3 + 0], y = xb[j * 3 + 1], z = xb[j * 3 + 2];
        pts[j] = make_float4(x, y, z, x * x + y * y + z * z);
    }
    __syncthreads();

    const int warp = threadIdx.x >> 5, lane = threadIdx.x & 31;
    const int p = blockIdx.x * 8 + warp;
    const float* q = nxyz + ((long)b * NP_ + p) * 3;
    const float qx = q[0], qy = q[1], qz = q[2];

    float4 c0 = pts[lane];
    float bestd = c0.w - 2.f * (qx * c0.x + qy * c0.y + qz * c0.z);
    int besti = lane;

    float curmax = bestd;
#pragma unroll
    for (int o = 16; o; o >>= 1) curmax = fmaxf(curmax, __shfl_xor_sync(FULL, curmax, o));

    for (int j0 = K_; j0 < N_; j0 += K_) {
        float4 c = pts[j0 + lane];
        float d = c.w - 2.f * (qx * c.x + qy * c.y + qz * c.z);
        unsigned mset = __ballot_sync(FULL, d < curmax);
        while (mset) {
            int src = __ffs(mset) - 1;
            mset &= mset - 1;
            float cd = __shfl_sync(FULL, d, src);
            if (cd < curmax) {
                unsigned vict = __ballot_sync(FULL, bestd == curmax);
                int vl = __ffs(vict) - 1;
                if (lane == vl) { bestd = cd; besti = j0 + src; }
                float v = bestd;
#pragma unroll
                for (int o = 16; o; o >>= 1) v = fmaxf(v, __shfl_xor_sync(FULL, v, o));
                curmax = v;
            }
        }
    }
    g_idx_buf[((long)b * NP_ + p) * K_ + lane] = besti;
}

// ============================================================================
// K2: fused group -> LN -> Q GEMM (register-tiled) -> collapsed K/V attention
// -> proj+dense. 512 threads, G_=4 groups per block, 1 block/SM.
// ============================================================================
struct __align__(16) SmemAttn {
    float xsT[CG][XP];          // 4 groups x (32 rows + pad), transposed
    float pad0[2];              // -> qm 16B-aligned
    float qm[G_][C_];           // column-max of q, per group
    float gmax[G_][132];        // max over K of raw gf, per group
    float z[G_][H_][132];       // qm . Wk
    float y[G_][H_][132];       // attnw . x
    float attnw[G_][H_][K_];    // softmax weights
    float sat[G_][C_];          // attention output (pre-proj)
    float qmP[16][C_];          // per-rowchunk q col-max partials
    int   nidx[G_][K_];
    float q3[G_][4];
};

__global__ void __launch_bounds__(T_, 1) attn_kernel(
    const float* __restrict__ xyz, const float* __restrict__ nxyz,
    const float* __restrict__ featin, const float* __restrict__ wqkv,
    const float* __restrict__ projw, const float* __restrict__ projb,
    const float* __restrict__ densew, const float* __restrict__ denseb,
    const float* __restrict__ n1g, const float* __restrict__ n1b) {
    SmemAttn& s = *reinterpret_cast<SmemAttn*>(dynsm);
    const int t = threadIdx.x;
    const int grp0 = blockIdx.x * G_;
    const int b = grp0 >> 10, p0 = grp0 & 1023;

    if (t < G_ * K_) {
        int g = t >> 5, r = t & 31;
        s.nidx[g][r] = g_idx_buf[(long)(grp0 + g) * K_ + r];
    }
    if (t < G_ * 3) {
        int g = t / 3, c = t % 3;
        s.q3[g][c] = nxyz[((long)b * NP_ + p0 + g) * 3 + c];
    }
    __syncthreads();

    // gather: relative xyz (rows 0..2) + features (rows 3..130)
    if (t < G_ * K_) {
        int g = t >> 5, r = t & 31;
        int j = s.nidx[g][r];
        const float* xp = xyz + ((long)b * N_ + j) * 3;
        s.xsT[0][g * GP + r] = xp[0] - s.q3[g][0];
        s.xsT[1][g * GP + r] = xp[1] - s.q3[g][1];
        s.xsT[2][g * GP + r] = xp[2] - s.q3[g][2];
    }
    for (int e = t; e < G_ * K_ * CIN; e += T_) {
        int g = e >> 12, r = (e >> 7) & 31, i = e & 127;
        s.xsT[3 + i][g * GP + r] = featin[((long)b * N_ + s.nidx[g][r]) * CIN + i];
    }
    __syncthreads();

    // max over K of raw gf (dense branch) before LN overwrites
    for (int e = t; e < G_ * CG; e += T_) {
        int g = e / CG, i = e - g * CG;
        float m = s.xsT[i][g * GP];
#pragma unroll
        for (int r = 1; r < K_; ++r) m = fmaxf(m, s.xsT[i][g * GP + r]);
        s.gmax[g][i] = m;
    }
    __syncthreads();

    // LayerNorm over CG=131 per row; warp w (0..15) owns rows w+16k
    {
        const int w = t >> 5, l = t & 31;
        for (int k = 0; k < 8; ++k) {
            const int row = w + 16 * k;
            const int g = row >> 5, r = row & 31;
            float v[5];
            int kn = 0;
            float sum = 0.f;
            for (int ii = l; ii < CG; ii += 32) { v[kn] = s.xsT[ii][g * GP + r]; sum += v[kn]; ++kn; }
#pragma unroll
            for (int o = 16; o; o >>= 1) sum += __shfl_xor_sync(FULL, sum, o);
            const float m = sum * (1.f / CG);
            float qv = 0.f;
            for (int kk = 0; kk < kn; ++kk) { float d = v[kk] - m; qv += d * d; }
#pragma unroll
            for (int o = 16; o; o >>= 1) qv += __shfl_xor_sync(FULL, qv, o);
            const float rs = rsqrtf(qv * (1.f / CG) + 1e-3f);
            kn = 0;
            for (int ii = l; ii < CG; ii += 32) {
                s.xsT[ii][g * GP + r] = (v[kn] - m) * rs * n1g[ii] + n1b[ii];
                ++kn;
            }
        }
    }
    __syncthreads();

    // ---- Q GEMM, register-tiled: warp w = 8-row chunk (group w>>2, local
    // chunk w&3); lane l owns cols {4l..4l+3} and {128+4l..128+4l+3}.
    // Per k-step: 4 broadcast LDS.64 + 2 coalesced LDG.128 + 32 fma2.
    {
        const int w = t >> 5, l = t & 31;
        const int xoff = (w >> 2) * GP + (w & 3) * 8;
        const float* wA = wqkv + 4 * l;
        const float* wB = wqkv + 128 + 4 * l;
        ull acc[8][4];
#pragma unroll
        for (int j = 0; j < 8; ++j)
#pragma unroll
            for (int rp = 0; rp < 4; ++rp) acc[j][rp] = 0ull;
        float4 cA = *reinterpret_cast<const float4*>(wA);
        float4 cB = *reinterpret_cast<const float4*>(wB);
#pragma unroll 1
        for (int i = 0; i < CG; ++i) {
            const long nx = (long)((i + 1 < CG) ? i + 1 : i) * TC;
            const float4 nA = *reinterpret_cast<const float4*>(wA + nx);
            const float4 nB = *reinterpret_cast<const float4*>(wB + nx);
            const ull* xr = reinterpret_cast<const ull*>(&s.xsT[i][xoff]);
            const ull x0 = xr[0], x1 = xr[1], x2 = xr[2], x3 = xr[3];
            ull w2;
            w2 = pk2(cA.x, cA.x);
            fma2(acc[0][0], x0, w2); fma2(acc[0][1], x1, w2); fma2(acc[0][2], x2, w2); fma2(acc[0][3], x3, w2);
            w2 = pk2(cA.y, cA.y);
            fma2(acc[1][0], x0, w2); fma2(acc[1][1], x1, w2); fma2(acc[1][2], x2, w2); fma2(acc[1][3], x3, w2);
            w2 = pk2(cA.z, cA.z);
            fma2(acc[2][0], x0, w2); fma2(acc[2][1], x1, w2); fma2(acc[2][2], x2, w2); fma2(acc[2][3], x3, w2);
            w2 = pk2(cA.w, cA.w);
            fma2(acc[3][0], x0, w2); fma2(acc[3][1], x1, w2); fma2(acc[3][2], x2, w2); fma2(acc[3][3], x3, w2);
            w2 = pk2(cB.x, cB.x);
            fma2(acc[4][0], x0, w2); fma2(acc[4][1], x1, w2); fma2(acc[4][2], x2, w2); fma2(acc[4][3], x3, w2);
            w2 = pk2(cB.y, cB.y);
            fma2(acc[5][0], x0, w2); fma2(acc[5][1], x1, w2); fma2(acc[5][2], x2, w2); fma2(acc[5][3], x3, w2);
            w2 = pk2(cB.z, cB.z);
            fma2(acc[6][0], x0, w2); fma2(acc[6][1], x1, w2); fma2(acc[6][2], x2, w2); fma2(acc[6][3], x3, w2);
            w2 = pk2(cB.w, cB.w);
            fma2(acc[7][0], x0, w2); fma2(acc[7][1], x1, w2); fma2(acc[7][2], x2, w2); fma2(acc[7][3], x3, w2);
            cA = nA; cB = nB;
        }
#pragma unroll
        for (int j = 0; j < 8; ++j) {
            float m = -1e30f;
#pragma unroll
            for (int rp = 0; rp < 4; ++rp) {
                float a, b2; upk2(acc[j][rp], a, b2);
                m = fmaxf(m, fmaxf(a, b2));
            }
            const int col = (j < 4) ? (4 * l + j) : (128 + 4 * l + (j - 4));
            s.qmP[w][col] = m;
        }
    }
    __syncthreads();

    // reduce qmP over the 4 row-chunks of each group
    for (int e = t; e < G_ * C_; e += T_) {
        const int g = e >> 8, c = e & 255;
        const float m = fmaxf(fmaxf(s.qmP[4 * g][c], s.qmP[4 * g + 1][c]),
                              fmaxf(s.qmP[4 * g + 2][c], s.qmP[4 * g + 3][c]));
        s.qm[g][c] = m;
    }
    __syncthreads();

    // ---- z[g][h][i] = sum_d qm[g][h*64+d] * Wk[i][h*64+d]; warp-per-i
    {
        const int w = t >> 5, l = t & 31;
        float4 qa[G_], qb[G_];
#pragma unroll
        for (int g = 0; g < G_; ++g) {
            qa[g] = reinterpret_cast<const float4*>(s.qm[g])[l];
            qb[g] = reinterpret_cast<const float4*>(s.qm[g])[32 + l];
        }
        for (int i = w; i < CG; i += 16) {
            const float4* wr = reinterpret_cast<const float4*>(wqkv + (long)i * TC + C_);
            const float4 w0 = wr[l];
            const float4 w1 = wr[32 + l];
            float s0[G_], s1[G_];
#pragma unroll
            for (int g = 0; g < G_; ++g) {
                s0[g] = w0.x * qa[g].x + w0.y * qa[g].y + w0.z * qa[g].z + w0.w * qa[g].w;
                s1[g] = w1.x * qb[g].x + w1.y * qb[g].y + w1.z * qb[g].z + w1.w * qb[g].w;
            }
#pragma unroll
            for (int o = 8; o; o >>= 1) {
#pragma unroll
                for (int g = 0; g < G_; ++g) {
                    s0[g] += __shfl_xor_sync(FULL, s0[g], o);
                    s1[g] += __shfl_xor_sync(FULL, s1[g], o);
                }
            }
            if ((l & 15) == 0) {
                const int h0 = l >> 4;
#pragma unroll
                for (int g = 0; g < G_; ++g) {
                    s.z[g][h0][i]     = s0[g];
                    s.z[g][h0 + 2][i] = s1[g];
                }
            }
        }
    }
    __syncthreads();

    // ---- logits + softmax: warp wh = (g,h), lane = row r (16 warps exactly)
    {
        const int wh = t >> 5;
        const int g = wh >> 2, h = wh & 3, r = t & 31;
        float a = 0.f;
#pragma unroll 4
        for (int i = 0; i < CG; ++i) a += s.xsT[i][g * GP + r] * s.z[g][h][i];
        a *= 0.0625f;  // C^-0.5
        float mx = a;
#pragma unroll
        for (int o = 16; o; o >>= 1) mx = fmaxf(mx, __shfl_xor_sync(FULL, mx, o));
        const float e = expf(a - mx);
        float ss = e;
#pragma unroll
        for (int o = 16; o; o >>= 1) ss += __shfl_xor_sync(FULL, ss, o);
        s.attnw[g][h][r] = e / ss;
    }
    __syncthreads();

    // ---- y[g][h][i] = sum_r attnw[g][h][r] * x[i][r]
    for (int e = t; e < G_ * H_ * CG; e += T_) {
        const int i = e % CG;
        const int gh = e / CG;
        const int g = gh >> 2, h = gh & 3;
        const ull* aw = reinterpret_cast<const ull*>(s.attnw[g][h]);
        const ull* xr = reinterpret_cast<const ull*>(&s.xsT[i][g * GP]);
        ull acc = 0ull;
#pragma unroll
        for (int rp = 0; rp < 16; ++rp) fma2(acc, xr[rp], aw[rp]);
        float a, b2; upk2(acc, a, b2);
        s.y[g][h][i] = a + b2;
    }
    __syncthreads();

    // ---- sat[g][c] = sum_i y[g][h][i] * Wv[i][c]; thread = (c, group-pair)
    {
        const int c = t & 255, g2 = t >> 8;        // groups g2, g2+2
        const int h = c >> 6;
        const float* wv = wqkv + 2 * C_ + c;
        float a0 = 0.f, a1 = 0.f;
#pragma unroll 8
        for (int i = 0; i < CG; ++i) {
            const float wvi = wv[(long)i * TC];
            a0 += s.y[g2][h][i] * wvi;
            a1 += s.y[g2 + 2][h][i] * wvi;
        }
        s.sat[g2][c] = a0;
        s.sat[g2 + 2][c] = a1;
    }
    __syncthreads();

    // ---- proj (relu) + dense (relu): thread = (c, group-pair)
    {
        const int c = t & 255, g2 = t >> 8;
        float p0 = 0.f, p1 = 0.f;
        const float* wp = projw + c;
#pragma unroll 8
        for (int i = 0; i < C_; ++i) {
            const float w = wp[(long)i * C_];
            p0 += s.sat[g2][i] * w;
            p1 += s.sat[g2 + 2][i] * w;
        }
        float d0 = 0.f, d1 = 0.f;
        const float* wd = densew + c;
#pragma unroll 8
        for (int i = 0; i < CG; ++i) {
            const float w = wd[(long)i * C_];
            d0 += s.gmax[g2][i] * w;
            d1 += s.gmax[g2 + 2][i] * w;
        }
        const float pb = projb[c], db = denseb[c];
        g_feat_buf[(long)(grp0 + g2) * C_ + c]     = fmaxf(p0 + pb, 0.f) + fmaxf(d0 + db, 0.f);
        g_feat_buf[(long)(grp0 + g2 + 2) * C_ + c] = fmaxf(p1 + pb, 0.f) + fmaxf(d1 + db, 0.f);
    }
}

// ============================================================================
// K3: LN2 -> fc1(relu) -> fc2 -> +feat. RPB=16 rows/block, register-tiled.
// ============================================================================
__global__ void __launch_bounds__(256) mlp_kernel(
    const float* __restrict__ fc1w, const float* __restrict__ fc1b,
    const float* __restrict__ fc2w, const float* __restrict__ fc2b,
    const float* __restrict__ n2g, const float* __restrict__ n2b,
    float* __restrict__ out) {
    ull*   lnDup = reinterpret_cast<ull*>(dynsm);                  // [256][17]
    float* hS    = reinterpret_cast<float*>(dynsm + 256 * 17 * 8); // [16][520]
    const int t = threadIdx.x;
    const long row0 = (long)blockIdx.x * RPB;

    // LN per row: warp w handles rows w and w+8
    {
        const int w = t >> 5, l = t & 31;
        for (int rr = 0; rr < 2; ++rr) {
            const int r = w + 8 * rr;
            const float* frow = g_feat_buf + (row0 + r) * C_;
            float v[8], sum = 0.f;
#pragma unroll
            for (int k = 0; k < 8; ++k) { v[k] = frow[l + 32 * k]; sum += v[k]; }
#pragma unroll
            for (int o = 16; o; o >>= 1) sum += __shfl_xor_sync(FULL, sum, o);
            const float m = sum * (1.f / C_);
            float qv = 0.f;
#pragma unroll
            for (int k = 0; k < 8; ++k) { float d = v[k] - m; qv += d * d; }
#pragma unroll
            for (int o = 16; o; o >>= 1) qv += __shfl_xor_sync(FULL, qv, o);
            const float rs = rsqrtf(qv * (1.f / C_) + 1e-3f);
#pragma unroll
            for (int k = 0; k < 8; ++k) {
                const int i = l + 32 * k;
                const float x = (v[k] - m) * rs * n2g[i] + n2b[i];
                lnDup[i * 17 + r] = pk2(x, x);
            }
        }
    }
    __syncthreads();

    const int q  = t >> 6;   // row group: rows 4q..4q+3
    const int cc = t & 63;

    // fc1: cols cc*8 .. cc*8+7 (4 col-pairs) x 4 rows
    {
        ull acc[4][4];
#pragma unroll
        for (int cp = 0; cp < 4; ++cp)
#pragma unroll
            for (int r = 0; r < 4; ++r) acc[cp][r] = 0ull;
        const float* wbase = fc1w + cc * 8;
#pragma unroll 1
        for (int i = 0; i < C_; ++i) {
            const ulonglong4 wv = *reinterpret_cast<const ulonglong4*>(wbase + (long)i * (2 * C_));
            const ull x0 = lnDup[i * 17 + 4 * q + 0];
            const ull x1 = lnDup[i * 17 + 4 * q + 1];
            const ull x2 = lnDup[i * 17 + 4 * q + 2];
            const ull x3 = lnDup[i * 17 + 4 * q + 3];
            fma2(acc[0][0], wv.x, x0); fma2(acc[0][1], wv.x, x1);
            fma2(acc[0][2], wv.x, x2); fma2(acc[0][3], wv.x, x3);
            fma2(acc[1][0], wv.y, x0); fma2(acc[1][1], wv.y, x1);
            fma2(acc[1][2], wv.y, x2); fma2(acc[1][3], wv.y, x3);
            fma2(acc[2][0], wv.z, x0); fma2(acc[2][1], wv.z, x1);
            fma2(acc[2][2], wv.z, x2); fma2(acc[2][3], wv.z, x3);
            fma2(acc[3][0], wv.w, x0); fma2(acc[3][1], wv.w, x1);
            fma2(acc[3][2], wv.w, x2); fma2(acc[3][3], wv.w, x3);
        }
        const float4 bA = *reinterpret_cast<const float4*>(fc1b + cc * 8);
        const float4 bB = *reinterpret_cast<const float4*>(fc1b + cc * 8 + 4);
        const float bias[8] = {bA.x, bA.y, bA.z, bA.w, bB.x, bB.y, bB.z, bB.w};
#pragma unroll
        for (int cp = 0; cp < 4; ++cp) {
            const int c0 = cc * 8 + 2 * cp;
#pragma unroll
            for (int r = 0; r < 4; ++r) {
                float a, b2; upk2(acc[cp][r], a, b2);
                hS[(4 * q + r) * 520 + c0]     = fmaxf(a + bias[2 * cp], 0.f);
                hS[(4 * q + r) * 520 + c0 + 1] = fmaxf(b2 + bias[2 * cp + 1], 0.f);
            }
        }
    }
    __syncthreads();

    // fc2: cols cc*4 .. cc*4+3 (2 col-pairs) x 4 rows, K=512
    {
        ull acc[2][4];
#pragma unroll
        for (int cp = 0; cp < 2; ++cp)
#pragma unroll
            for (int r = 0; r < 4; ++r) acc[cp][r] = 0ull;
        const float* wbase = fc2w + cc * 4;
#pragma unroll 2
        for (int j = 0; j < 2 * C_; ++j) {
            const ulonglong2 wv = *reinterpret_cast<const ulonglong2*>(wbase + (long)j * C_);
            const float h0 = hS[(4 * q + 0) * 520 + j];
            const float h1 = hS[(4 * q + 1) * 520 + j];
            const float h2 = hS[(4 * q + 2) * 520 + j];
            const float h3 = hS[(4 * q + 3) * 520 + j];
            const ull x0 = pk2(h0, h0), x1 = pk2(h1, h1), x2 = pk2(h2, h2), x3 = pk2(h3, h3);
            fma2(acc[0][0], wv.x, x0); fma2(acc[0][1], wv.x, x1);
            fma2(acc[0][2], wv.x, x2); fma2(acc[0][3], wv.x, x3);
            fma2(acc[1][0], wv.y, x0); fma2(acc[1][1], wv.y, x1);
            fma2(acc[1][2], wv.y, x2); fma2(acc[1][3], wv.y, x3);
        }
        const float4 bias = *reinterpret_cast<const float4*>(fc2b + cc * 4);
#pragma unroll
        for (int r = 0; r < 4; ++r) {
            const long row = row0 + 4 * q + r;
            const float4 res = *reinterpret_cast<const float4*>(g_feat_buf + row * C_ + cc * 4);
            float a0, a1, a2, a3;
            upk2(acc[0][r], a0, a1);
            upk2(acc[1][r], a2, a3);
            float4 o;
            o.x = a0 + bias.x + res.x;
            o.y = a1 + bias.y + res.y;
            o.z = a2 + bias.z + res.z;
            o.w = a3 + bias.w + res.w;
            *reinterpret_cast<float4*>(out + row * C_ + cc * 4) = o;
        }
    }
}

// ============================================================================
extern "C" void kernel_launch(void* const* d_in, const int* in_sizes, int n_in,
                              void* d_out, int out_size) {
    const float* xyz    = (const float*)d_in[0];
    const float* nxyz   = (const float*)d_in[1];
    const float* featin = (const float*)d_in[2];
    const float* wqkv   = (const float*)d_in[3];
    const float* projw  = (const float*)d_in[4];
    const float* projb  = (const float*)d_in[5];
    const float* densew = (const float*)d_in[6];
    const float* denseb = (const float*)d_in[7];
    const float* fc1w   = (const float*)d_in[8];
    const float* fc1b   = (const float*)d_in[9];
    const float* fc2w   = (const float*)d_in[10];
    const float* fc2b   = (const float*)d_in[11];
    const float* n1g    = (const float*)d_in[12];
    const float* n1b    = (const float*)d_in[13];
    const float* n2g    = (const float*)d_in[14];
    const float* n2b    = (const float*)d_in[15];
    float* out = (float*)d_out;

    (void)in_sizes; (void)n_in; (void)out_size;

    const int knn_smem  = N_ * (int)sizeof(float4);            // 64 KB
    const int attn_smem = (int)sizeof(SmemAttn);               // ~116 KB
    const int mlp_smem  = 256 * 17 * 8 + 16 * 520 * 4;         // ~68 KB
    cudaFuncSetAttribute(knn_kernel, cudaFuncAttributeMaxDynamicSharedMemorySize, knn_smem);
    cudaFuncSetAttribute(attn_kernel, cudaFuncAttributeMaxDynamicSharedMemorySize, attn_smem);
    cudaFuncSetAttribute(mlp_kernel, cudaFuncAttributeMaxDynamicSharedMemorySize, mlp_smem);

    knn_kernel<<<dim3(NP_ / 8, B_), 256, knn_smem>>>(xyz, nxyz);
    attn_kernel<<<B_ * NP_ / G_, T_, attn_smem>>>(xyz, nxyz, featin, wqkv, projw, projb,
                                                  densew, denseb, n1g, n1b);
    mlp_kernel<<<B_ * NP_ / RPB, 256, mlp_smem>>>(fc1w, fc1b, fc2w, fc2b, n2g, n2b, out);
}

// round 8
// speedup vs baseline: 1.7192x; 1.2211x over previous
#include <cuda_runtime.h>
#include <cuda_bf16.h>
#include <cstdint>

typedef unsigned long long ull;
#define FULL 0xffffffffu

constexpr int B_  = 16;
constexpr int N_  = 4096;
constexpr int NP_ = 1024;
constexpr int K_  = 32;
constexpr int CIN = 128;
constexpr int CG  = 131;   // 3 + 128
constexpr int C_  = 256;
constexpr int H_  = 4;
constexpr int D_  = 64;
constexpr int TC  = 768;   // 3*C
constexpr int G_  = 4;     // groups per attn block (M = 128 rows)
constexpr int GP  = 34;    // per-group sub-pitch (floats) in xsT row
constexpr int XP  = 138;   // xsT row pitch (floats)
constexpr int T_  = 512;   // attn threads
constexpr int RPB = 16;    // rows per block in mlp kernel
constexpr int KC  = 48;    // K-chunk for mma (3 chunks: 144 >= 131, zero pad)
constexpr int AP  = 26;    // A/B smem row pitch in 32-bit words (conflict-free)

// scratch (device globals: allocation-free rule)
__device__ int   g_idx_buf[B_ * NP_ * K_];
__device__ float g_feat_buf[B_ * NP_ * C_];
// Wq as bf16 hi/lo, [chunk][part][n=256][24 words of k-pairs]
__device__ __align__(16) unsigned g_wq[3 * 2 * 256 * 24];

extern __shared__ __align__(16) unsigned char dynsm[];

// ---------------- packed f32x2 helpers
__device__ __forceinline__ ull pk2(float a, float b) {
    ull r;
    asm("mov.b64 %0, {%1,%2};" : "=l"(r) : "f"(a), "f"(b));
    return r;
}
__device__ __forceinline__ void upk2(ull v, float& a, float& b) {
    asm("mov.b64 {%0,%1}, %2;" : "=f"(a), "=f"(b) : "l"(v));
}
__device__ __forceinline__ void fma2(ull& d, ull a, ull b) {
    asm("fma.rn.f32x2 %0, %1, %2, %3;" : "=l"(d) : "l"(a), "l"(b), "l"(d));
}

// ---------------- warp mma m16n8k16 bf16 (base PTX, works at compute_103)
__device__ __forceinline__ void mma16816(float* d, const unsigned* a, unsigned b0, unsigned b1) {
    asm volatile(
        "mma.sync.aligned.m16n8k16.row.col.f32.bf16.bf16.f32 "
        "{%0,%1,%2,%3}, {%4,%5,%6,%7}, {%8,%9}, {%0,%1,%2,%3};"
        : "+f"(d[0]), "+f"(d[1]), "+f"(d[2]), "+f"(d[3])
        : "r"(a[0]), "r"(a[1]), "r"(a[2]), "r"(a[3]), "r"(b0), "r"(b1));
}
__device__ __forceinline__ unsigned bf16pair(float x0, float x1) {
    const __nv_bfloat16 h0 = __float2bfloat16(x0), h1 = __float2bfloat16(x1);
    return (unsigned)__bfloat16_as_ushort(h0) | ((unsigned)__bfloat16_as_ushort(h1) << 16);
}

// ============================================================================
// K0: prep — Wq (131x256 fp32, k-major rows) -> bf16 hi/lo, [c][part][n][24w],
// k padded to 144 with zeros.
// ============================================================================
__global__ void __launch_bounds__(512) prep_kernel(const float* __restrict__ wqkv) {
    const int idx = blockIdx.x * 512 + threadIdx.x;
    if (idx >= 3 * 256 * 24) return;
    const int c = idx / 6144;
    const int rem = idx % 6144;
    const int n = rem / 24, j = rem % 24;
    const int k = c * KC + 2 * j;
    const float x0 = (k < CG) ? wqkv[(long)k * TC + n] : 0.f;
    const float x1 = (k + 1 < CG) ? wqkv[(long)(k + 1) * TC + n] : 0.f;
    const __nv_bfloat16 h0 = __float2bfloat16(x0), h1 = __float2bfloat16(x1);
    const float r0 = x0 - __bfloat162float(h0), r1 = x1 - __bfloat162float(h1);
    g_wq[(c * 2 + 0) * 6144 + n * 24 + j] = bf16pair(x0, x1);   // hi (rounded inside)
    g_wq[(c * 2 + 1) * 6144 + n * 24 + j] = bf16pair(r0, r1);   // lo
}

// ============================================================================
// K1: KNN. One warp per query, max-replacement top-32 (set-only).
// ============================================================================
__global__ void __launch_bounds__(256) knn_kernel(const float* __restrict__ xyz,
                                                  const float* __restrict__ nxyz) {
    float4* pts = reinterpret_cast<float4*>(dynsm);
    const int b = blockIdx.y;
    const float* xb = xyz + (long)b * N_ * 3;
    for (int j = threadIdx.x; j < N_; j += 256) {
        float x = xb[j * 3 + 0], y = xb[j * 3 + 1], z = xb[j * 3 + 2];
        pts[j] = make_float4(x, y, z, x * x + y * y + z * z);
    }
    __syncthreads();

    const int warp = threadIdx.x >> 5, lane = threadIdx.x & 31;
    const int p = blockIdx.x * 8 + warp;
    const float* q = nxyz + ((long)b * NP_ + p) * 3;
    const float qx = q[0], qy = q[1], qz = q[2];

    float4 c0 = pts[lane];
    float bestd = c0.w - 2.f * (qx * c0.x + qy * c0.y + qz * c0.z);
    int besti = lane;

    float curmax = bestd;
#pragma unroll
    for (int o = 16; o; o >>= 1) curmax = fmaxf(curmax, __shfl_xor_sync(FULL, curmax, o));

    for (int j0 = K_; j0 < N_; j0 += K_) {
        float4 c = pts[j0 + lane];
        float d = c.w - 2.f * (qx * c.x + qy * c.y + qz * c.z);
        unsigned mset = __ballot_sync(FULL, d < curmax);
        while (mset) {
            int src = __ffs(mset) - 1;
            mset &= mset - 1;
            float cd = __shfl_sync(FULL, d, src);
            if (cd < curmax) {
                unsigned vict = __ballot_sync(FULL, bestd == curmax);
                int vl = __ffs(vict) - 1;
                if (lane == vl) { bestd = cd; besti = j0 + src; }
                float v = bestd;
#pragma unroll
                for (int o = 16; o; o >>= 1) v = fmaxf(v, __shfl_xor_sync(FULL, v, o));
                curmax = v;
            }
        }
    }
    g_idx_buf[((long)b * NP_ + p) * K_ + lane] = besti;
}

// ============================================================================
// K2: fused group -> LN -> Q GEMM (mma.sync bf16 split) -> collapsed K/V
// attention -> proj+dense. M=128 (4 groups x 32 rows), N=256, K=131(->144).
// ============================================================================
struct __align__(16) SmemAll {
    unsigned Abf[2][128][AP];   // x bf16 hi/lo, one 48-K chunk, [m][k-pair words]
    unsigned Bbf[2][256][AP];   // Wq bf16 hi/lo, one chunk, [n][k-pair words]
    float xsT[CG][XP];          // LN'd grouped features, transposed
    float pad0[2];
    float qm[G_][C_];
    float gmax[G_][132];
    float z[G_][H_][132];
    float y[G_][H_][132];
    float attnw[G_][H_][K_];
    float sat[G_][C_];
    int   nidx[G_][K_];
    float q3[G_][4];
};

__global__ void __launch_bounds__(T_, 1) attn_kernel(
    const float* __restrict__ xyz, const float* __restrict__ nxyz,
    const float* __restrict__ featin, const float* __restrict__ wqkv,
    const float* __restrict__ projw, const float* __restrict__ projb,
    const float* __restrict__ densew, const float* __restrict__ denseb,
    const float* __restrict__ n1g, const float* __restrict__ n1b) {
    SmemAll& s = *reinterpret_cast<SmemAll*>(dynsm);
    const int t = threadIdx.x;
    const int w = t >> 5, lane = t & 31;
    const int grp0 = blockIdx.x * G_;
    const int b = grp0 >> 10, p0 = grp0 & 1023;

    if (t < G_ * K_) {
        int g = t >> 5, r = t & 31;
        s.nidx[g][r] = g_idx_buf[(long)(grp0 + g) * K_ + r];
    }
    if (t < G_ * 3) {
        int g = t / 3, c = t % 3;
        s.q3[g][c] = nxyz[((long)b * NP_ + p0 + g) * 3 + c];
    }
    __syncthreads();

    // gather: relative xyz (rows 0..2) + features (rows 3..130)
    if (t < G_ * K_) {
        int g = t >> 5, r = t & 31;
        int j = s.nidx[g][r];
        const float* xp = xyz + ((long)b * N_ + j) * 3;
        s.xsT[0][g * GP + r] = xp[0] - s.q3[g][0];
        s.xsT[1][g * GP + r] = xp[1] - s.q3[g][1];
        s.xsT[2][g * GP + r] = xp[2] - s.q3[g][2];
    }
    for (int e = t; e < G_ * K_ * CIN; e += T_) {
        int g = e >> 12, r = (e >> 7) & 31, i = e & 127;
        s.xsT[3 + i][g * GP + r] = featin[((long)b * N_ + s.nidx[g][r]) * CIN + i];
    }
    __syncthreads();

    // max over K of raw gf (dense branch) before LN overwrites
    for (int e = t; e < G_ * CG; e += T_) {
        int g = e / CG, i = e - g * CG;
        float m = s.xsT[i][g * GP];
#pragma unroll
        for (int r = 1; r < K_; ++r) m = fmaxf(m, s.xsT[i][g * GP + r]);
        s.gmax[g][i] = m;
    }
    __syncthreads();

    // LayerNorm over CG=131 per row; warp w (0..15) owns rows w+16k
    for (int k = 0; k < 8; ++k) {
        const int row = w + 16 * k;
        const int g = row >> 5, r = row & 31;
        float v[5];
        int kn = 0;
        float sum = 0.f;
        for (int ii = lane; ii < CG; ii += 32) { v[kn] = s.xsT[ii][g * GP + r]; sum += v[kn]; ++kn; }
#pragma unroll
        for (int o = 16; o; o >>= 1) sum += __shfl_xor_sync(FULL, sum, o);
        const float m = sum * (1.f / CG);
        float qv = 0.f;
        for (int kk = 0; kk < kn; ++kk) { float d = v[kk] - m; qv += d * d; }
#pragma unroll
        for (int o = 16; o; o >>= 1) qv += __shfl_xor_sync(FULL, qv, o);
        const float rs = rsqrtf(qv * (1.f / CG) + 1e-3f);
        kn = 0;
        for (int ii = lane; ii < CG; ii += 32) {
            s.xsT[ii][g * GP + r] = (v[kn] - m) * rs * n1g[ii] + n1b[ii];
            ++kn;
        }
    }
    __syncthreads();

    // ================= Q GEMM on tensor cores (mma.sync, split bf16) ========
    // warp w: group g = w&3 (rows 32g..32g+31 = m-tiles 2), n-cols (w>>2)*64..+63
    const int gq = w & 3;
    const int mbase = 32 * gq;
    const int nbase = (w >> 2) * 64;
    const int lp = lane >> 2, lq = lane & 3;
    float cfr[2][8][4];
#pragma unroll
    for (int mt = 0; mt < 2; ++mt)
#pragma unroll
        for (int j = 0; j < 8; ++j)
#pragma unroll
            for (int e = 0; e < 4; ++e) cfr[mt][j][e] = 0.f;

    const unsigned* A0 = &s.Abf[0][0][0];
    const unsigned* A1 = &s.Abf[1][0][0];
    const unsigned* B0 = &s.Bbf[0][0][0];
    const unsigned* B1 = &s.Bbf[1][0][0];

    for (int c = 0; c < 3; ++c) {
        // --- convert A chunk c: xsT fp32 -> bf16 hi/lo pairs
        {
            const int mq = t & 127;
            const int qd = t >> 7;
            const int colx = (mq >> 5) * GP + (mq & 31);
#pragma unroll
            for (int jj = 0; jj < 6; ++jj) {
                const int j = qd * 6 + jj;
                const int k = c * KC + 2 * j;
                const float x0 = (k < CG) ? s.xsT[k][colx] : 0.f;
                const float x1 = (k + 1 < CG) ? s.xsT[k + 1][colx] : 0.f;
                const __nv_bfloat16 h0 = __float2bfloat16(x0), h1 = __float2bfloat16(x1);
                s.Abf[0][mq][j] = (unsigned)__bfloat16_as_ushort(h0) |
                                  ((unsigned)__bfloat16_as_ushort(h1) << 16);
                s.Abf[1][mq][j] = bf16pair(x0 - __bfloat162float(h0), x1 - __bfloat162float(h1));
            }
        }
        // --- copy B chunk c (hi+lo), re-pitch 24 -> 26 words
        {
            const uint2* src = reinterpret_cast<const uint2*>(g_wq) + (long)c * 6144;
            uint2* dst = reinterpret_cast<uint2*>(&s.Bbf[0][0][0]);
            for (int i = t; i < 6144; i += T_) {
                const int row = i / 12, j2 = i % 12;
                dst[row * 13 + j2] = src[i];
            }
        }
        __syncthreads();

        // --- 3 k-steps of m16n8k16, products hh + hl + lh
#pragma unroll
        for (int ks = 0; ks < 3; ++ks) {
            const int ko = ks * 8 + lq;
            unsigned ah[2][4], al[2][4];
#pragma unroll
            for (int mt = 0; mt < 2; ++mt) {
                const int r0 = (mbase + mt * 16 + lp) * AP;
                const int r8 = r0 + 8 * AP;
                ah[mt][0] = A0[r0 + ko];     ah[mt][1] = A0[r8 + ko];
                ah[mt][2] = A0[r0 + ko + 4]; ah[mt][3] = A0[r8 + ko + 4];
                al[mt][0] = A1[r0 + ko];     al[mt][1] = A1[r8 + ko];
                al[mt][2] = A1[r0 + ko + 4]; al[mt][3] = A1[r8 + ko + 4];
            }
#pragma unroll
            for (int j = 0; j < 8; ++j) {
                const int nr = (nbase + j * 8 + lp) * AP;
                const unsigned bh0 = B0[nr + ko], bh1 = B0[nr + ko + 4];
                const unsigned bl0 = B1[nr + ko], bl1 = B1[nr + ko + 4];
#pragma unroll
                for (int mt = 0; mt < 2; ++mt) {
                    mma16816(cfr[mt][j], ah[mt], bh0, bh1);
                    mma16816(cfr[mt][j], ah[mt], bl0, bl1);
                    mma16816(cfr[mt][j], al[mt], bh0, bh1);
                }
            }
        }
        __syncthreads();
    }

    // per-group column max from C fragments: cols 2*lq (+1), rows via lanes
#pragma unroll
    for (int j = 0; j < 8; ++j) {
        float ve = fmaxf(fmaxf(cfr[0][j][0], cfr[0][j][2]), fmaxf(cfr[1][j][0], cfr[1][j][2]));
        float vo = fmaxf(fmaxf(cfr[0][j][1], cfr[0][j][3]), fmaxf(cfr[1][j][1], cfr[1][j][3]));
#pragma unroll
        for (int o = 4; o <= 16; o <<= 1) {
            ve = fmaxf(ve, __shfl_xor_sync(FULL, ve, o));
            vo = fmaxf(vo, __shfl_xor_sync(FULL, vo, o));
        }
        if (lane < 4) {
            s.qm[gq][nbase + j * 8 + 2 * lane]     = ve;
            s.qm[gq][nbase + j * 8 + 2 * lane + 1] = vo;
        }
    }
    __syncthreads();

    // ---- z[g][h][i] = sum_d qm[g][h*64+d] * Wk[i][h*64+d]; warp-per-i
    {
        float4 qa[G_], qb[G_];
#pragma unroll
        for (int g = 0; g < G_; ++g) {
            qa[g] = reinterpret_cast<const float4*>(s.qm[g])[lane];
            qb[g] = reinterpret_cast<const float4*>(s.qm[g])[32 + lane];
        }
        for (int i = w; i < CG; i += 16) {
            const float4* wr = reinterpret_cast<const float4*>(wqkv + (long)i * TC + C_);
            const float4 w0 = wr[lane];
            const float4 w1 = wr[32 + lane];
            float s0[G_], s1[G_];
#pragma unroll
            for (int g = 0; g < G_; ++g) {
                s0[g] = w0.x * qa[g].x + w0.y * qa[g].y + w0.z * qa[g].z + w0.w * qa[g].w;
                s1[g] = w1.x * qb[g].x + w1.y * qb[g].y + w1.z * qb[g].z + w1.w * qb[g].w;
            }
#pragma unroll
            for (int o = 8; o; o >>= 1) {
#pragma unroll
                for (int g = 0; g < G_; ++g) {
                    s0[g] += __shfl_xor_sync(FULL, s0[g], o);
                    s1[g] += __shfl_xor_sync(FULL, s1[g], o);
                }
            }
            if ((lane & 15) == 0) {
                const int h0 = lane >> 4;
#pragma unroll
                for (int g = 0; g < G_; ++g) {
                    s.z[g][h0][i]     = s0[g];
                    s.z[g][h0 + 2][i] = s1[g];
                }
            }
        }
    }
    __syncthreads();

    // ---- logits + softmax: warp w = (g,h), lane = row r
    {
        const int g = w >> 2, h = w & 3, r = lane;
        float a = 0.f;
#pragma unroll 4
        for (int i = 0; i < CG; ++i) a += s.xsT[i][g * GP + r] * s.z[g][h][i];
        a *= 0.0625f;
        float mx = a;
#pragma unroll
        for (int o = 16; o; o >>= 1) mx = fmaxf(mx, __shfl_xor_sync(FULL, mx, o));
        const float e = expf(a - mx);
        float ss = e;
#pragma unroll
        for (int o = 16; o; o >>= 1) ss += __shfl_xor_sync(FULL, ss, o);
        s.attnw[g][h][r] = e / ss;
    }
    __syncthreads();

    // ---- y[g][h][i] = sum_r attnw[g][h][r] * x[i][r]
    for (int e = t; e < G_ * H_ * CG; e += T_) {
        const int i = e % CG;
        const int gh = e / CG;
        const int g = gh >> 2, h = gh & 3;
        const ull* aw = reinterpret_cast<const ull*>(s.attnw[g][h]);
        const ull* xr = reinterpret_cast<const ull*>(&s.xsT[i][g * GP]);
        ull acc = 0ull;
#pragma unroll
        for (int rp = 0; rp < 16; ++rp) fma2(acc, xr[rp], aw[rp]);
        float a, b2; upk2(acc, a, b2);
        s.y[g][h][i] = a + b2;
    }
    __syncthreads();

    // ---- sat[g][c] = sum_i y[g][h][i] * Wv[i][c]; thread = (c, group-pair)
    {
        const int c = t & 255, g2 = t >> 8;
        const int h = c >> 6;
        const float* wv = wqkv + 2 * C_ + c;
        float a0 = 0.f, a1 = 0.f;
#pragma unroll 8
        for (int i = 0; i < CG; ++i) {
            const float wvi = wv[(long)i * TC];
            a0 += s.y[g2][h][i] * wvi;
            a1 += s.y[g2 + 2][h][i] * wvi;
        }
        s.sat[g2][c] = a0;
        s.sat[g2 + 2][c] = a1;
    }
    __syncthreads();

    // ---- proj (relu) + dense (relu): thread = (c, group-pair)
    {
        const int c = t & 255, g2 = t >> 8;
        float p0 = 0.f, p1 = 0.f;
        const float* wp = projw + c;
#pragma unroll 8
        for (int i = 0; i < C_; ++i) {
            const float wv = wp[(long)i * C_];
            p0 += s.sat[g2][i] * wv;
            p1 += s.sat[g2 + 2][i] * wv;
        }
        float d0 = 0.f, d1 = 0.f;
        const float* wd = densew + c;
#pragma unroll 8
        for (int i = 0; i < CG; ++i) {
            const float wv = wd[(long)i * C_];
            d0 += s.gmax[g2][i] * wv;
            d1 += s.gmax[g2 + 2][i] * wv;
        }
        const float pb = projb[c], db = denseb[c];
        g_feat_buf[(long)(grp0 + g2) * C_ + c]     = fmaxf(p0 + pb, 0.f) + fmaxf(d0 + db, 0.f);
        g_feat_buf[(long)(grp0 + g2 + 2) * C_ + c] = fmaxf(p1 + pb, 0.f) + fmaxf(d1 + db, 0.f);
    }
}

// ============================================================================
// K3: LN2 -> fc1(relu) -> fc2 -> +feat. RPB=16 rows/block, register-tiled.
// ============================================================================
__global__ void __launch_bounds__(256) mlp_kernel(
    const float* __restrict__ fc1w, const float* __restrict__ fc1b,
    const float* __restrict__ fc2w, const float* __restrict__ fc2b,
    const float* __restrict__ n2g, const float* __restrict__ n2b,
    float* __restrict__ out) {
    ull*   lnDup = reinterpret_cast<ull*>(dynsm);                  // [256][17]
    float* hS    = reinterpret_cast<float*>(dynsm + 256 * 17 * 8); // [16][520]
    const int t = threadIdx.x;
    const long row0 = (long)blockIdx.x * RPB;

    {
        const int w = t >> 5, l = t & 31;
        for (int rr = 0; rr < 2; ++rr) {
            const int r = w + 8 * rr;
            const float* frow = g_feat_buf + (row0 + r) * C_;
            float v[8], sum = 0.f;
#pragma unroll
            for (int k = 0; k < 8; ++k) { v[k] = frow[l + 32 * k]; sum += v[k]; }
#pragma unroll
            for (int o = 16; o; o >>= 1) sum += __shfl_xor_sync(FULL, sum, o);
            const float m = sum * (1.f / C_);
            float qv = 0.f;
#pragma unroll
            for (int k = 0; k < 8; ++k) { float d = v[k] - m; qv += d * d; }
#pragma unroll
            for (int o = 16; o; o >>= 1) qv += __shfl_xor_sync(FULL, qv, o);
            const float rs = rsqrtf(qv * (1.f / C_) + 1e-3f);
#pragma unroll
            for (int k = 0; k < 8; ++k) {
                const int i = l + 32 * k;
                const float x = (v[k] - m) * rs * n2g[i] + n2b[i];
                lnDup[i * 17 + r] = pk2(x, x);
            }
        }
    }
    __syncthreads();

    const int q  = t >> 6;
    const int cc = t & 63;

    {
        ull acc[4][4];
#pragma unroll
        for (int cp = 0; cp < 4; ++cp)
#pragma unroll
            for (int r = 0; r < 4; ++r) acc[cp][r] = 0ull;
        const float* wbase = fc1w + cc * 8;
#pragma unroll 1
        for (int i = 0; i < C_; ++i) {
            const ulonglong4 wv = *reinterpret_cast<const ulonglong4*>(wbase + (long)i * (2 * C_));
            const ull x0 = lnDup[i * 17 + 4 * q + 0];
            const ull x1 = lnDup[i * 17 + 4 * q + 1];
            const ull x2 = lnDup[i * 17 + 4 * q + 2];
            const ull x3 = lnDup[i * 17 + 4 * q + 3];
            fma2(acc[0][0], wv.x, x0); fma2(acc[0][1], wv.x, x1);
            fma2(acc[0][2], wv.x, x2); fma2(acc[0][3], wv.x, x3);
            fma2(acc[1][0], wv.y, x0); fma2(acc[1][1], wv.y, x1);
            fma2(acc[1][2], wv.y, x2); fma2(acc[1][3], wv.y, x3);
            fma2(acc[2][0], wv.z, x0); fma2(acc[2][1], wv.z, x1);
            fma2(acc[2][2], wv.z, x2); fma2(acc[2][3], wv.z, x3);
            fma2(acc[3][0], wv.w, x0); fma2(acc[3][1], wv.w, x1);
            fma2(acc[3][2], wv.w, x2); fma2(acc[3][3], wv.w, x3);
        }
        const float4 bA = *reinterpret_cast<const float4*>(fc1b + cc * 8);
        const float4 bB = *reinterpret_cast<const float4*>(fc1b + cc * 8 + 4);
        const float bias[8] = {bA.x, bA.y, bA.z, bA.w, bB.x, bB.y, bB.z, bB.w};
#pragma unroll
        for (int cp = 0; cp < 4; ++cp) {
            const int c0 = cc * 8 + 2 * cp;
#pragma unroll
            for (int r = 0; r < 4; ++r) {
                float a, b2; upk2(acc[cp][r], a, b2);
                hS[(4 * q + r) * 520 + c0]     = fmaxf(a + bias[2 * cp], 0.f);
                hS[(4 * q + r) * 520 + c0 + 1] = fmaxf(b2 + bias[2 * cp + 1], 0.f);
            }
        }
    }
    __syncthreads();

    {
        ull acc[2][4];
#pragma unroll
        for (int cp = 0; cp < 2; ++cp)
#pragma unroll
            for (int r = 0; r < 4; ++r) acc[cp][r] = 0ull;
        const float* wbase = fc2w + cc * 4;
#pragma unroll 2
        for (int j = 0; j < 2 * C_; ++j) {
            const ulonglong2 wv = *reinterpret_cast<const ulonglong2*>(wbase + (long)j * C_);
            const float h0 = hS[(4 * q + 0) * 520 + j];
            const float h1 = hS[(4 * q + 1) * 520 + j];
            const float h2 = hS[(4 * q + 2) * 520 + j];
            const float h3 = hS[(4 * q + 3) * 520 + j];
            const ull x0 = pk2(h0, h0), x1 = pk2(h1, h1), x2 = pk2(h2, h2), x3 = pk2(h3, h3);
            fma2(acc[0][0], wv.x, x0); fma2(acc[0][1], wv.x, x1);
            fma2(acc[0][2], wv.x, x2); fma2(acc[0][3], wv.x, x3);
            fma2(acc[1][0], wv.y, x0); fma2(acc[1][1], wv.y, x1);
            fma2(acc[1][2], wv.y, x2); fma2(acc[1][3], wv.y, x3);
        }
        const float4 bias = *reinterpret_cast<const float4*>(fc2b + cc * 4);
#pragma unroll
        for (int r = 0; r < 4; ++r) {
            const long row = row0 + 4 * q + r;
            const float4 res = *reinterpret_cast<const float4*>(g_feat_buf + row * C_ + cc * 4);
            float a0, a1, a2, a3;
            upk2(acc[0][r], a0, a1);
            upk2(acc[1][r], a2, a3);
            float4 o;
            o.x = a0 + bias.x + res.x;
            o.y = a1 + bias.y + res.y;
            o.z = a2 + bias.z + res.z;
            o.w = a3 + bias.w + res.w;
            *reinterpret_cast<float4*>(out + row * C_ + cc * 4) = o;
        }
    }
}

// ============================================================================
extern "C" void kernel_launch(void* const* d_in, const int* in_sizes, int n_in,
                              void* d_out, int out_size) {
    const float* xyz    = (const float*)d_in[0];
    const float* nxyz   = (const float*)d_in[1];
    const float* featin = (const float*)d_in[2];
    const float* wqkv   = (const float*)d_in[3];
    const float* projw  = (const float*)d_in[4];
    const float* projb  = (const float*)d_in[5];
    const float* densew = (const float*)d_in[6];
    const float* denseb = (const float*)d_in[7];
    const float* fc1w   = (const float*)d_in[8];
    const float* fc1b   = (const float*)d_in[9];
    const float* fc2w   = (const float*)d_in[10];
    const float* fc2b   = (const float*)d_in[11];
    const float* n1g    = (const float*)d_in[12];
    const float* n1b    = (const float*)d_in[13];
    const float* n2g    = (const float*)d_in[14];
    const float* n2b    = (const float*)d_in[15];
    float* out = (float*)d_out;

    (void)in_sizes; (void)n_in; (void)out_size;

    const int knn_smem  = N_ * (int)sizeof(float4);            // 64 KB
    const int attn_smem = (int)sizeof(SmemAll);                // ~178 KB
    const int mlp_smem  = 256 * 17 * 8 + 16 * 520 * 4;         // ~68 KB
    cudaFuncSetAttribute(knn_kernel, cudaFuncAttributeMaxDynamicSharedMemorySize, knn_smem);
    cudaFuncSetAttribute(attn_kernel, cudaFuncAttributeMaxDynamicSharedMemorySize, attn_smem);
    cudaFuncSetAttribute(mlp_kernel, cudaFuncAttributeMaxDynamicSharedMemorySize, mlp_smem);

    prep_kernel<<<36, 512>>>(wqkv);
    knn_kernel<<<dim3(NP_ / 8, B_), 256, knn_smem>>>(xyz, nxyz);
    attn_kernel<<<B_ * NP_ / G_, T_, attn_smem>>>(xyz, nxyz, featin, wqkv, projw, projb,
                                                  densew, denseb, n1g, n1b);
    mlp_kernel<<<B_ * NP_ / RPB, 256, mlp_smem>>>(fc1w, fc1b, fc2w, fc2b, n2g, n2b, out);
}